// round 6
// baseline (speedup 1.0000x reference)
#include <cuda_runtime.h>

// PixelWiseRNN: h_t = tanh(w_ih*x_t + b_ih + w_hh*h_{t-1} + b_hh), h_0 = 0
// x: (B, T, Z, H, W) fp32, params: (Z, H, W) fp32, out: (B, T, Z, H, W) fp32
// B=4, T=256, Z=16, H=64, W=64  ->  P = Z*H*W = 65536 pixels per batch.
//
// R5: compute is free (issue 20%, MUFU.TANH chain) but DRAM stuck at 73% ->
// per-warp MLP too low. Process time in blocks of 8: batch-issue 8 LDGs
// (1 KB/warp in flight), run the 8-step serial chain, batch 8 STGs.
// Doubles in-flight bytes and groups HBM read/write directions.

#define RNN_B 4
#define RNN_T 256
#define RNN_P 65536   // Z*H*W
#define TB 8          // timesteps per body

__device__ __forceinline__ float hw_tanh(float z)
{
    float r;
    asm("tanh.approx.f32 %0, %1;" : "=f"(r) : "f"(z));
    return r;
}

__global__ __launch_bounds__(256) void pixel_rnn_kernel(
    const float* __restrict__ x,
    const float* __restrict__ w_ih,
    const float* __restrict__ w_hh,
    const float* __restrict__ b_ih,
    const float* __restrict__ b_hh,
    float* __restrict__ out)
{
    const int gid = blockIdx.x * blockDim.x + threadIdx.x;   // [0, B*P)
    const int b = gid >> 16;          // gid / P
    const int p = gid & (RNN_P - 1);  // gid % P

    const float wi   = w_ih[p];
    const float wh   = w_hh[p];
    const float bias = b_ih[p] + b_hh[p];

    const size_t base = (size_t)b * RNN_T * RNN_P + p;
    const float* __restrict__ xp = x + base;
    float* __restrict__ op = out + base;

    float h = 0.0f;

    for (int tb = 0; tb < RNN_T; tb += TB) {
        // Phase 1: batch-issue all TB loads (independent -> MLP = TB).
        float xv[TB];
        #pragma unroll
        for (int i = 0; i < TB; i++)
            xv[i] = xp[(size_t)(tb + i) * RNN_P];

        // Phase 2: serial recurrence over the TB steps (cheap: FFMA+FFMA+MUFU.TANH).
        float hv[TB];
        #pragma unroll
        for (int i = 0; i < TB; i++) {
            const float a = fmaf(wi, xv[i], bias);
            h = hw_tanh(fmaf(wh, h, a));
            hv[i] = h;
        }

        // Phase 3: batch the TB stores.
        #pragma unroll
        for (int i = 0; i < TB; i++)
            op[(size_t)(tb + i) * RNN_P] = hv[i];
    }
}

extern "C" void kernel_launch(void* const* d_in, const int* in_sizes, int n_in,
                              void* d_out, int out_size)
{
    const float* x    = (const float*)d_in[0];
    const float* w_ih = (const float*)d_in[1];
    const float* w_hh = (const float*)d_in[2];
    const float* b_ih = (const float*)d_in[3];
    const float* b_hh = (const float*)d_in[4];
    float* out = (float*)d_out;

    const int total_threads = RNN_B * RNN_P;   // 262144
    const int block = 256;
    const int grid = total_threads / block;    // 1024

    pixel_rnn_kernel<<<grid, block>>>(x, w_ih, w_hh, b_ih, b_hh, out);
}